// round 8
// baseline (speedup 1.0000x reference)
#include <cuda_runtime.h>
#include <cuda_bf16.h>
#include <cstdint>

#define N_NODES 100000
#define N_EDGES 6400000
#define LOG2_10 3.3219280948873623f

// Scratch accumulator (allocation-free rule: __device__ global).
__device__ float d_syn[N_NODES];

// ---------------------------------------------------------------------------
// Phase 0: zero the accumulator (must be re-zeroed every call: graph replays).
// ---------------------------------------------------------------------------
__global__ void zero_syn_kernel() {
    int i = blockIdx.x * blockDim.x + threadIdx.x;
    if (i < N_NODES) d_syn[i] = 0.0f;
}

// ---------------------------------------------------------------------------
// Phase 1: edge scatter. 4 edges per thread via vectorized loads.
// Skip the atomic entirely when the destination is an input node (its syn is
// discarded by the where()), halving L2 atomic traffic.
// is_input is int32 (bool promoted by the harness).
// ---------------------------------------------------------------------------
__global__ void __launch_bounds__(256) edge_kernel(
    const float* __restrict__ rates,
    const float* __restrict__ weights,
    const int*   __restrict__ src,
    const int*   __restrict__ dst,
    const int*   __restrict__ is_input)
{
    const int e4 = blockIdx.x * blockDim.x + threadIdx.x;   // 0 .. E/4-1
    if (e4 >= N_EDGES / 4) return;

    const int4   s = __ldg(reinterpret_cast<const int4*>(src) + e4);
    const int4   d = __ldg(reinterpret_cast<const int4*>(dst) + e4);
    const float4 w = __ldg(reinterpret_cast<const float4*>(weights) + e4);

    // Predicate on destination being a non-input node.
    const bool p0 = (__ldg(is_input + d.x) == 0);
    const bool p1 = (__ldg(is_input + d.y) == 0);
    const bool p2 = (__ldg(is_input + d.z) == 0);
    const bool p3 = (__ldg(is_input + d.w) == 0);

    if (p0) atomicAdd(&d_syn[d.x], __ldg(rates + s.x) * w.x);
    if (p1) atomicAdd(&d_syn[d.y], __ldg(rates + s.y) * w.y);
    if (p2) atomicAdd(&d_syn[d.z], __ldg(rates + s.z) * w.z);
    if (p3) atomicAdd(&d_syn[d.w], __ldg(rates + s.w) * w.w);
}

// ---------------------------------------------------------------------------
// Phase 2: per-node epilogue.
// total = (is_input ? ext : syn) + baseline
// out   = (-r + 10^gain * tanh(total)) / tau
// ---------------------------------------------------------------------------
__global__ void __launch_bounds__(256) node_kernel(
    const float* __restrict__ rates,
    const float* __restrict__ gain,
    const float* __restrict__ tau,
    const float* __restrict__ baseline,
    const float* __restrict__ ext_input,
    const int*   __restrict__ is_input,
    float* __restrict__ out)
{
    int i = blockIdx.x * blockDim.x + threadIdx.x;
    if (i >= N_NODES) return;

    const float syn   = d_syn[i];
    const float ext   = __ldg(ext_input + i);
    const float total = (__ldg(is_input + i) ? ext : syn) + __ldg(baseline + i);
    const float act   = tanhf(total);
    const float g     = exp2f(__ldg(gain + i) * LOG2_10);   // 10^gain
    out[i] = (-__ldg(rates + i) + g * act) / __ldg(tau + i);
}

// ---------------------------------------------------------------------------
// Launch. Input order (metadata): rates, weights, gain, time_constant,
// baseline, ext_input, src, dst, is_input. Output: float32[N_NODES].
// ---------------------------------------------------------------------------
extern "C" void kernel_launch(void* const* d_in, const int* in_sizes, int n_in,
                              void* d_out, int out_size)
{
    const float* rates    = (const float*)d_in[0];
    const float* weights  = (const float*)d_in[1];
    const float* gain     = (const float*)d_in[2];
    const float* tau      = (const float*)d_in[3];
    const float* baseline = (const float*)d_in[4];
    const float* ext      = (const float*)d_in[5];
    const int*   src      = (const int*)d_in[6];
    const int*   dst      = (const int*)d_in[7];
    const int*   is_input = (const int*)d_in[8];
    float* out = (float*)d_out;

    const int node_blocks = (N_NODES + 255) / 256;
    const int edge_blocks = (N_EDGES / 4 + 255) / 256;

    zero_syn_kernel<<<node_blocks, 256>>>();
    edge_kernel<<<edge_blocks, 256>>>(rates, weights, src, dst, is_input);
    node_kernel<<<node_blocks, 256>>>(rates, gain, tau, baseline, ext, is_input, out);
}